// round 1
// baseline (speedup 1.0000x reference)
#include <cuda_runtime.h>
#include <cuda_bf16.h>
#include <math.h>

// Problem constants
#define EMBED   512
#define HIDDEN  512
#define VOCAB   32000
#define NLAYERS 2
#define BATCH   32
#define SEQ     64
#define STEPS   (SEQ - 1)          // 63
#define COMBK   (EMBED + HIDDEN)   // 1024
#define MROWS   (STEPS * BATCH)    // 2016

// ---------------- scratch (no allocations allowed) ----------------
// h/c double-buffered by step parity: step t reads parity (t&1), writes (t&1)^1.
__device__ float g_h[2][NLAYERS * BATCH * HIDDEN];
__device__ float g_c[2][NLAYERS * BATCH * HIDDEN];
// h of the last layer for every step, laid out as A matrix: row m = t*32 + b
__device__ float g_hstore[MROWS * HIDDEN];

__device__ __forceinline__ float sigmoidf_(float x) {
    return 1.0f / (1.0f + expf(-x));
}

// ---------------- init: h0 = feat @ ihw^T + ihb ; c0 likewise ----------------
// grid = 32 (batch), block = 256
__global__ void init_kernel(const float* __restrict__ features,
                            const float* __restrict__ ihw, const float* __restrict__ ihb,
                            const float* __restrict__ icw, const float* __restrict__ icb) {
    __shared__ float feat[EMBED];
    int b = blockIdx.x;
    for (int i = threadIdx.x; i < EMBED; i += blockDim.x)
        feat[i] = features[b * EMBED + i];
    __syncthreads();

    for (int j = threadIdx.x; j < HIDDEN; j += blockDim.x) {
        float ah = ihb[j];
        float ac = icb[j];
        const float4* wh = (const float4*)(ihw + (size_t)j * EMBED);
        const float4* wc = (const float4*)(icw + (size_t)j * EMBED);
        #pragma unroll 4
        for (int e4 = 0; e4 < EMBED / 4; e4++) {
            float4 h4 = wh[e4];
            float4 c4 = wc[e4];
            const float* f = &feat[e4 * 4];
            ah += f[0]*h4.x + f[1]*h4.y + f[2]*h4.z + f[3]*h4.w;
            ac += f[0]*c4.x + f[1]*c4.y + f[2]*c4.z + f[3]*c4.w;
        }
        // both layers start from the same state, written to parity 0
        g_h[0][(0 * BATCH + b) * HIDDEN + j] = ah;
        g_h[0][(1 * BATCH + b) * HIDDEN + j] = ah;
        g_c[0][(0 * BATCH + b) * HIDDEN + j] = ac;
        g_c[0][(1 * BATCH + b) * HIDDEN + j] = ac;
    }
}

// ---------------- one LSTM (step, layer) phase ----------------
// grid = 128 (4 hidden units each), block = 128 threads.
// Thread (b = tid&31, g = tid>>5) accumulates 4 units for gate g, batch b.
// Fuses: gates GEMM (M=32, N=4units x 4gates, K=1024) + bias + activations + state update.
#define KT  128   // k-tile
#define UPB 4     // units per block

__global__ __launch_bounds__(128)
void lstm_step_kernel(const float* __restrict__ embw,      // 32000 x 512
                      const int*   __restrict__ captions,  // 32 x 64
                      const float* __restrict__ Wf, const float* __restrict__ Wi,
                      const float* __restrict__ Wo, const float* __restrict__ Wc,
                      const float* __restrict__ Bf, const float* __restrict__ Bi,
                      const float* __restrict__ Bo, const float* __restrict__ Bc,
                      int l, int t, int pr, int pw) {
    __shared__ float comb_s[KT][33];           // [k][b], padded: conflict-free reads
    __shared__ float w_s[4][UPB][KT];          // [gate][unit][k]
    __shared__ float gate_s[4][UPB][BATCH];    // [gate][unit][b]

    const int tid = threadIdx.x;
    const int b  = tid & 31;
    const int g  = tid >> 5;                   // 0=f 1=i 2=o 3=c~
    const int u0 = blockIdx.x * UPB;

    const float* Wg = (g == 0) ? Wf : (g == 1) ? Wi : (g == 2) ? Wo : Wc;
    const float* Bg = (g == 0) ? Bf : (g == 1) ? Bi : (g == 2) ? Bo : Bc;

    float acc[UPB] = {0.f, 0.f, 0.f, 0.f};

    for (int kt = 0; kt < COMBK / KT; kt++) {
        const int k0 = kt * KT;
        __syncthreads();   // previous tile fully consumed

        // ---- load comb tile: comb[b][k0..k0+KT) -> comb_s[k][b] ----
        // warp-uniform row per j-iter: b_row = 4j + (tid>>5), lane = float4 col
        #pragma unroll
        for (int j = 0; j < 8; j++) {
            int b_row = 4 * j + (tid >> 5);
            int col4  = tid & 31;
            const float* src;
            int kk;
            if (k0 < EMBED) {            // x part of comb
                kk = k0;
                if (l == 0) {
                    int tok = captions[b_row * SEQ + t];
                    src = embw + (size_t)tok * EMBED;
                } else {
                    // x for layer1 = layer0's freshly written h (parity pw)
                    src = &g_h[pw][(0 * BATCH + b_row) * HIDDEN];
                }
            } else {                     // h part of comb (old h of this layer)
                kk = k0 - EMBED;
                src = &g_h[pr][(l * BATCH + b_row) * HIDDEN];
            }
            float4 v = *(const float4*)&src[kk + 4 * col4];
            int kl = 4 * col4;
            comb_s[kl + 0][b_row] = v.x;
            comb_s[kl + 1][b_row] = v.y;
            comb_s[kl + 2][b_row] = v.z;
            comb_s[kl + 3][b_row] = v.w;
        }

        // ---- load weight tile: gate j, unit = warp id ----
        {
            int w = tid >> 5;
            int col4 = tid & 31;
            #pragma unroll
            for (int j = 0; j < 4; j++) {
                const float* W = (j == 0) ? Wf : (j == 1) ? Wi : (j == 2) ? Wo : Wc;
                float4 v = *(const float4*)&W[(size_t)(u0 + w) * COMBK + k0 + 4 * col4];
                *(float4*)&w_s[j][w][4 * col4] = v;
            }
        }
        __syncthreads();

        // ---- FMA: 4 k's x 4 units per iter ----
        #pragma unroll 8
        for (int k = 0; k < KT; k += 4) {
            float c0 = comb_s[k + 0][b];
            float c1 = comb_s[k + 1][b];
            float c2 = comb_s[k + 2][b];
            float c3 = comb_s[k + 3][b];
            #pragma unroll
            for (int u = 0; u < UPB; u++) {
                float4 w4 = *(const float4*)&w_s[g][u][k];
                acc[u] += c0 * w4.x + c1 * w4.y + c2 * w4.z + c3 * w4.w;
            }
        }
    }

    // bias + exchange gates through smem
    #pragma unroll
    for (int u = 0; u < UPB; u++)
        gate_s[g][u][b] = acc[u] + Bg[u0 + u];
    __syncthreads();

    // elementwise state update: thread -> (b2 = tid&31, u = tid>>5)
    {
        int b2 = tid & 31;
        int u  = tid >> 5;
        int j  = u0 + u;
        float f  = sigmoidf_(gate_s[0][u][b2]);
        float i  = sigmoidf_(gate_s[1][u][b2]);
        float o  = sigmoidf_(gate_s[2][u][b2]);
        float ct = tanhf    (gate_s[3][u][b2]);
        int sidx = (l * BATCH + b2) * HIDDEN + j;
        float cold = g_c[pr][sidx];
        float cnew = f * cold + i * ct;
        float hnew = o * tanhf(cnew);
        g_c[pw][sidx] = cnew;
        g_h[pw][sidx] = hnew;
        if (l == NLAYERS - 1)
            g_hstore[(size_t)(t * BATCH + b2) * HIDDEN + j] = hnew;
    }
}

// ---------------- logits: C[2016][32000] = hstore @ out_w^T + out_b ----------------
// classic fp32 SGEMM, BM=BN=128, BK=8, 8x8 microtile, 256 threads
#define BM 128
#define BN 128
#define BKL 8

__global__ __launch_bounds__(256)
void logits_kernel(const float* __restrict__ Bw,     // out_w 32000 x 512
                   const float* __restrict__ bias,   // 32000
                   float* __restrict__ out) {        // (32, 63, 32000)
    __shared__ float As[BKL][BM];
    __shared__ float Bs[BKL][BN];

    const int tid = threadIdx.x;
    const int m0 = blockIdx.y * BM;
    const int n0 = blockIdx.x * BN;

    const int lm = tid >> 1;           // 0..127 : row within tile for loads
    const int lk = (tid & 1) * 4;      // 0 or 4 : k offset for float4 load

    const int msub = (tid >> 4) * 8;   // 0..120
    const int nsub = (tid & 15) * 8;   // 0..120

    float acc[8][8];
    #pragma unroll
    for (int i = 0; i < 8; i++)
        #pragma unroll
        for (int j = 0; j < 8; j++) acc[i][j] = 0.f;

    for (int k0 = 0; k0 < HIDDEN; k0 += BKL) {
        float4 av = make_float4(0.f, 0.f, 0.f, 0.f);
        int gm = m0 + lm;
        if (gm < MROWS)
            av = *(const float4*)&g_hstore[(size_t)gm * HIDDEN + k0 + lk];
        float4 bv = *(const float4*)&Bw[(size_t)(n0 + lm) * HIDDEN + k0 + lk];

        __syncthreads();  // previous tile consumed
        As[lk + 0][lm] = av.x; As[lk + 1][lm] = av.y;
        As[lk + 2][lm] = av.z; As[lk + 3][lm] = av.w;
        Bs[lk + 0][lm] = bv.x; Bs[lk + 1][lm] = bv.y;
        Bs[lk + 2][lm] = bv.z; Bs[lk + 3][lm] = bv.w;
        __syncthreads();

        #pragma unroll
        for (int k = 0; k < BKL; k++) {
            float a[8], bb[8];
            *(float4*)&a[0]  = *(const float4*)&As[k][msub];
            *(float4*)&a[4]  = *(const float4*)&As[k][msub + 4];
            *(float4*)&bb[0] = *(const float4*)&Bs[k][nsub];
            *(float4*)&bb[4] = *(const float4*)&Bs[k][nsub + 4];
            #pragma unroll
            for (int i = 0; i < 8; i++)
                #pragma unroll
                for (int j = 0; j < 8; j++)
                    acc[i][j] += a[i] * bb[j];
        }
    }

    // epilogue: row m = t*32 + b  ->  out[((b*63)+t)*32000 + n]
    float bvals[8];
    #pragma unroll
    for (int j = 0; j < 8; j++) bvals[j] = bias[n0 + nsub + j];

    #pragma unroll
    for (int i = 0; i < 8; i++) {
        int m = m0 + msub + i;
        if (m < MROWS) {
            int b = m & 31;
            int t = m >> 5;
            float* orow = out + ((size_t)(b * STEPS + t)) * VOCAB + n0 + nsub;
            float4 v0, v1;
            v0.x = acc[i][0] + bvals[0]; v0.y = acc[i][1] + bvals[1];
            v0.z = acc[i][2] + bvals[2]; v0.w = acc[i][3] + bvals[3];
            v1.x = acc[i][4] + bvals[4]; v1.y = acc[i][5] + bvals[5];
            v1.z = acc[i][6] + bvals[6]; v1.w = acc[i][7] + bvals[7];
            *(float4*)&orow[0] = v0;
            *(float4*)&orow[4] = v1;
        }
    }
}

// ---------------- launch ----------------
extern "C" void kernel_launch(void* const* d_in, const int* in_sizes, int n_in,
                              void* d_out, int out_size) {
    const float* features = (const float*)d_in[0];
    const int*   captions = (const int*)  d_in[1];
    const float* embw     = (const float*)d_in[2];
    const float* Wf       = (const float*)d_in[3];
    const float* bf       = (const float*)d_in[4];
    const float* Wi       = (const float*)d_in[5];
    const float* bi       = (const float*)d_in[6];
    const float* Wc       = (const float*)d_in[7];
    const float* bc       = (const float*)d_in[8];
    const float* Wo       = (const float*)d_in[9];
    const float* bo       = (const float*)d_in[10];
    const float* out_w    = (const float*)d_in[11];
    const float* out_b    = (const float*)d_in[12];
    const float* ihw      = (const float*)d_in[13];
    const float* ihb      = (const float*)d_in[14];
    const float* icw      = (const float*)d_in[15];
    const float* icb      = (const float*)d_in[16];
    float* out = (float*)d_out;

    init_kernel<<<BATCH, 256>>>(features, ihw, ihb, icw, icb);

    for (int t = 0; t < STEPS; t++) {
        int pr = t & 1;
        int pw = pr ^ 1;
        for (int l = 0; l < NLAYERS; l++) {
            size_t wofs = (size_t)l * HIDDEN * COMBK;
            size_t bofs = (size_t)l * HIDDEN;
            lstm_step_kernel<<<HIDDEN / UPB, 128>>>(
                embw, captions,
                Wf + wofs, Wi + wofs, Wo + wofs, Wc + wofs,
                bf + bofs, bi + bofs, bo + bofs, bc + bofs,
                l, t, pr, pw);
        }
    }

    dim3 grid(VOCAB / BN, (MROWS + BM - 1) / BM);  // 250 x 16
    logits_kernel<<<grid, 256>>>(out_w, out_b, out);
}

// round 4
// speedup vs baseline: 1.3468x; 1.3468x over previous
#include <cuda_runtime.h>
#include <cuda_bf16.h>
#include <cuda_fp16.h>
#include <math.h>
#include <stdint.h>

// Problem constants
#define EMBED   512
#define HIDDEN  512
#define VOCAB   32000
#define NLAYERS 2
#define BATCH   32
#define SEQ     64
#define STEPS   (SEQ - 1)          // 63
#define COMBK   (EMBED + HIDDEN)   // 1024
#define MROWS   (STEPS * BATCH)    // 2016
#define MPAD    2048
#define KP      1536               // split-K: [Ahi|Ahi|Alo] x [Bhi|Blo|Bhi]

// ---------------- scratch (no allocations allowed) ----------------
__device__ float g_h[2][NLAYERS * BATCH * HIDDEN];
__device__ float g_c[2][NLAYERS * BATCH * HIDDEN];
__device__ float g_hstore[MROWS * HIDDEN];
__device__ __half g_A[(size_t)MPAD * KP];      // 6.3 MB (padding rows stay zero)
__device__ __half g_B[(size_t)VOCAB * KP];     // 98 MB

__device__ __forceinline__ float sigmoidf_(float x) {
    return 1.0f / (1.0f + expf(-x));
}

// ================= PTX helpers (baseline ISA only; no tcgen05) =================
static __device__ __forceinline__ uint32_t smem_u32(const void* p) {
    uint32_t a;
    asm("{ .reg .u64 t; cvta.to.shared.u64 t, %1; cvt.u32.u64 %0, t; }" : "=r"(a) : "l"(p));
    return a;
}
static __device__ __forceinline__ void cp_async16(uint32_t dst, const void* src) {
    asm volatile("cp.async.cg.shared.global [%0], [%1], 16;" :: "r"(dst), "l"(src));
}
#define CP_COMMIT()  asm volatile("cp.async.commit_group;" ::: "memory")
#define CP_WAIT(n)   asm volatile("cp.async.wait_group %0;" :: "n"(n) : "memory")

static __device__ __forceinline__ void ldsm4(uint32_t* r, uint32_t addr) {
    asm volatile("ldmatrix.sync.aligned.m8n8.x4.shared.b16 {%0,%1,%2,%3}, [%4];"
                 : "=r"(r[0]), "=r"(r[1]), "=r"(r[2]), "=r"(r[3]) : "r"(addr));
}
static __device__ __forceinline__ void mma16816(float* c, const uint32_t* a,
                                                uint32_t b0, uint32_t b1) {
    asm volatile("mma.sync.aligned.m16n8k16.row.col.f32.f16.f16.f32 "
                 "{%0,%1,%2,%3}, {%4,%5,%6,%7}, {%8,%9}, {%0,%1,%2,%3};"
                 : "+f"(c[0]), "+f"(c[1]), "+f"(c[2]), "+f"(c[3])
                 : "r"(a[0]), "r"(a[1]), "r"(a[2]), "r"(a[3]), "r"(b0), "r"(b1));
}

// ---------------- init: h0 = feat @ ihw^T + ihb ; c0 likewise ----------------
__global__ void init_kernel(const float* __restrict__ features,
                            const float* __restrict__ ihw, const float* __restrict__ ihb,
                            const float* __restrict__ icw, const float* __restrict__ icb) {
    __shared__ float feat[EMBED];
    int b = blockIdx.x;
    for (int i = threadIdx.x; i < EMBED; i += blockDim.x)
        feat[i] = features[b * EMBED + i];
    __syncthreads();

    for (int j = threadIdx.x; j < HIDDEN; j += blockDim.x) {
        float ah = ihb[j];
        float ac = icb[j];
        const float4* wh = (const float4*)(ihw + (size_t)j * EMBED);
        const float4* wc = (const float4*)(icw + (size_t)j * EMBED);
        #pragma unroll 4
        for (int e4 = 0; e4 < EMBED / 4; e4++) {
            float4 h4 = wh[e4];
            float4 c4 = wc[e4];
            const float* f = &feat[e4 * 4];
            ah += f[0]*h4.x + f[1]*h4.y + f[2]*h4.z + f[3]*h4.w;
            ac += f[0]*c4.x + f[1]*c4.y + f[2]*c4.z + f[3]*c4.w;
        }
        g_h[0][(0 * BATCH + b) * HIDDEN + j] = ah;
        g_h[0][(1 * BATCH + b) * HIDDEN + j] = ah;
        g_c[0][(0 * BATCH + b) * HIDDEN + j] = ac;
        g_c[0][(1 * BATCH + b) * HIDDEN + j] = ac;
    }
}

// ---------------- one LSTM (step, layer) phase (unchanged, known good) ----------------
#define KT  128
#define UPB 4

__global__ __launch_bounds__(128)
void lstm_step_kernel(const float* __restrict__ embw,
                      const int*   __restrict__ captions,
                      const float* __restrict__ Wf, const float* __restrict__ Wi,
                      const float* __restrict__ Wo, const float* __restrict__ Wc,
                      const float* __restrict__ Bf, const float* __restrict__ Bi,
                      const float* __restrict__ Bo, const float* __restrict__ Bc,
                      int l, int t, int pr, int pw) {
    __shared__ float comb_s[KT][33];
    __shared__ float w_s[4][UPB][KT];
    __shared__ float gate_s[4][UPB][BATCH];

    const int tid = threadIdx.x;
    const int b  = tid & 31;
    const int g  = tid >> 5;
    const int u0 = blockIdx.x * UPB;

    const float* Bg = (g == 0) ? Bf : (g == 1) ? Bi : (g == 2) ? Bo : Bc;

    float acc[UPB] = {0.f, 0.f, 0.f, 0.f};

    for (int kt = 0; kt < COMBK / KT; kt++) {
        const int k0 = kt * KT;
        __syncthreads();

        #pragma unroll
        for (int j = 0; j < 8; j++) {
            int b_row = 4 * j + (tid >> 5);
            int col4  = tid & 31;
            const float* src;
            int kk;
            if (k0 < EMBED) {
                kk = k0;
                if (l == 0) {
                    int tok = captions[b_row * SEQ + t];
                    src = embw + (size_t)tok * EMBED;
                } else {
                    src = &g_h[pw][(0 * BATCH + b_row) * HIDDEN];
                }
            } else {
                kk = k0 - EMBED;
                src = &g_h[pr][(l * BATCH + b_row) * HIDDEN];
            }
            float4 v = *(const float4*)&src[kk + 4 * col4];
            int kl = 4 * col4;
            comb_s[kl + 0][b_row] = v.x;
            comb_s[kl + 1][b_row] = v.y;
            comb_s[kl + 2][b_row] = v.z;
            comb_s[kl + 3][b_row] = v.w;
        }

        {
            int w = tid >> 5;
            int col4 = tid & 31;
            #pragma unroll
            for (int j = 0; j < 4; j++) {
                const float* W = (j == 0) ? Wf : (j == 1) ? Wi : (j == 2) ? Wo : Wc;
                float4 v = *(const float4*)&W[(size_t)(u0 + w) * COMBK + k0 + 4 * col4];
                *(float4*)&w_s[j][w][4 * col4] = v;
            }
        }
        __syncthreads();

        #pragma unroll 8
        for (int k = 0; k < KT; k += 4) {
            float c0 = comb_s[k + 0][b];
            float c1 = comb_s[k + 1][b];
            float c2 = comb_s[k + 2][b];
            float c3 = comb_s[k + 3][b];
            #pragma unroll
            for (int u = 0; u < UPB; u++) {
                float4 w4 = *(const float4*)&w_s[g][u][k];
                acc[u] += c0 * w4.x + c1 * w4.y + c2 * w4.z + c3 * w4.w;
            }
        }
    }

    #pragma unroll
    for (int u = 0; u < UPB; u++)
        gate_s[g][u][b] = acc[u] + Bg[u0 + u];
    __syncthreads();

    {
        int b2 = tid & 31;
        int u  = tid >> 5;
        int j  = u0 + u;
        float f  = sigmoidf_(gate_s[0][u][b2]);
        float i  = sigmoidf_(gate_s[1][u][b2]);
        float o  = sigmoidf_(gate_s[2][u][b2]);
        float ct = tanhf    (gate_s[3][u][b2]);
        int sidx = (l * BATCH + b2) * HIDDEN + j;
        float cold = g_c[pr][sidx];
        float cnew = f * cold + i * ct;
        float hnew = o * tanhf(cnew);
        g_c[pw][sidx] = cnew;
        g_h[pw][sidx] = hnew;
        if (l == NLAYERS - 1)
            g_hstore[(size_t)(t * BATCH + b2) * HIDDEN + j] = hnew;
    }
}

// ---------------- fp32 -> fp16 hi/lo split conversions ----------------
// B'[n][0:512]=hi(W), [512:1024]=lo(W), [1024:1536]=hi(W)
__global__ __launch_bounds__(256)
void convB_kernel(const float* __restrict__ w) {
    size_t idx = (size_t)blockIdx.x * blockDim.x + threadIdx.x;
    if (idx >= (size_t)VOCAB * 512) return;
    int n = (int)(idx >> 9);
    int k = (int)(idx & 511);
    float x = w[idx];
    __half hi = __float2half_rn(x);
    __half lo = __float2half_rn(x - __half2float(hi));
    size_t base = (size_t)n * KP;
    g_B[base + k]        = hi;
    g_B[base + 512 + k]  = lo;
    g_B[base + 1024 + k] = hi;
}

// A'[m][0:512]=hi(h), [512:1024]=hi(h), [1024:1536]=lo(h)
__global__ __launch_bounds__(256)
void convA_kernel() {
    size_t idx = (size_t)blockIdx.x * blockDim.x + threadIdx.x;
    if (idx >= (size_t)MROWS * 512) return;
    int m = (int)(idx >> 9);
    int k = (int)(idx & 511);
    float x = g_hstore[idx];
    __half hi = __float2half_rn(x);
    __half lo = __float2half_rn(x - __half2float(hi));
    size_t base = (size_t)m * KP;
    g_A[base + k]        = hi;
    g_A[base + 512 + k]  = hi;
    g_A[base + 1024 + k] = lo;
}

// ---------------- logits via mma.sync: D[2048 x 32000] = A' @ B'^T + bias ----------------
// CTA tile 128x128, BK=64 halves (128B swizzled rows), cp.async double buffer.
// 8 warps = 4(m) x 2(n); warp tile 32x64; mma.sync.m16n8k16 f16->f32.
#define GBK       64
#define GNCH      (KP / GBK)         // 24
#define GTILE_B   16384              // 128 rows * 128 B
#define GBUF_B    (2 * GTILE_B)      // A+B per stage
#define SMEM_DYN  (2 * GBUF_B + 512) // 66048

__global__ __launch_bounds__(256)
void logits_hmma_kernel(const float* __restrict__ bias, float* __restrict__ out) {
    extern __shared__ __align__(128) char sm[];
    const uint32_t smu = smem_u32(sm);
    float* bias_s = (float*)(sm + 2 * GBUF_B);

    const int tid  = threadIdx.x;
    const int wid  = tid >> 5;
    const int lane = tid & 31;
    const int n0 = blockIdx.x * 128;
    const int m0 = blockIdx.y * 128;

    const int warp_m = (wid >> 1) * 32;
    const int warp_n = (wid & 1) * 64;

    // bias to smem
    if (tid < 128) bias_s[tid] = bias[n0 + tid];

    // ---- async chunk loader ----
    auto load_chunk = [&](int c) {
        const int buf = c & 1;
        const uint32_t sA = smu + buf * GBUF_B;
        const uint32_t sB = sA + GTILE_B;
        const __half* Ag = g_A + (size_t)m0 * KP + c * GBK;
        const __half* Bg = g_B + (size_t)n0 * KP + c * GBK;
        #pragma unroll
        for (int i = 0; i < 4; i++) {
            int idx = i * 256 + tid;         // 0..1023
            int r  = idx >> 3;
            int ch = idx & 7;
            uint32_t dst = (uint32_t)(r * 128) + (((uint32_t)(ch ^ (r & 7))) << 4);
            cp_async16(sA + dst, Ag + (size_t)r * KP + ch * 8);
            cp_async16(sB + dst, Bg + (size_t)r * KP + ch * 8);
        }
        CP_COMMIT();
    };

    float acc[2][8][4];
    #pragma unroll
    for (int mi = 0; mi < 2; mi++)
        #pragma unroll
        for (int ni = 0; ni < 8; ni++)
            #pragma unroll
            for (int q = 0; q < 4; q++) acc[mi][ni][q] = 0.f;

    load_chunk(0);
    load_chunk(1);

    for (int c = 0; c < GNCH; c++) {
        if (c + 1 < GNCH) { CP_WAIT(1); } else { CP_WAIT(0); }
        __syncthreads();

        const int buf = c & 1;
        const uint32_t sA = smu + buf * GBUF_B;
        const uint32_t sB = sA + GTILE_B;

        #pragma unroll
        for (int ks = 0; ks < GBK / 16; ks++) {
            uint32_t a[2][4];
            #pragma unroll
            for (int mi = 0; mi < 2; mi++) {
                int row = warp_m + mi * 16 + (lane & 15);
                int kc  = ks * 2 + (lane >> 4);
                uint32_t addr = sA + row * 128 + (((uint32_t)(kc ^ (row & 7))) << 4);
                ldsm4(a[mi], addr);
            }
            uint32_t b[4][4];
            #pragma unroll
            for (int nj = 0; nj < 4; nj++) {
                int row = warp_n + nj * 16 + (lane & 7) + ((lane >> 4) << 3);
                int kc  = ks * 2 + ((lane >> 3) & 1);
                uint32_t addr = sB + row * 128 + (((uint32_t)(kc ^ (row & 7))) << 4);
                ldsm4(b[nj], addr);
            }
            #pragma unroll
            for (int mi = 0; mi < 2; mi++)
                #pragma unroll
                for (int ni = 0; ni < 8; ni++) {
                    const uint32_t* bp = &b[ni >> 1][(ni & 1) * 2];
                    mma16816(acc[mi][ni], a[mi], bp[0], bp[1]);
                }
        }
        __syncthreads();
        if (c + 2 < GNCH) load_chunk(c + 2);
    }

    // ---- epilogue: bias + store in (b, t, v) order ----
    #pragma unroll
    for (int mi = 0; mi < 2; mi++) {
        int r0 = m0 + warp_m + mi * 16 + (lane >> 2);
        int r1 = r0 + 8;
        float* orow0 = nullptr;
        float* orow1 = nullptr;
        if (r0 < MROWS) {
            int bb = r0 & 31, tt = r0 >> 5;
            orow0 = out + (size_t)(bb * STEPS + tt) * VOCAB + n0;
        }
        if (r1 < MROWS) {
            int bb = r1 & 31, tt = r1 >> 5;
            orow1 = out + (size_t)(bb * STEPS + tt) * VOCAB + n0;
        }
        #pragma unroll
        for (int ni = 0; ni < 8; ni++) {
            int col = warp_n + ni * 8 + (lane & 3) * 2;
            float b0 = bias_s[col];
            float b1 = bias_s[col + 1];
            if (orow0) {
                float2 v; v.x = acc[mi][ni][0] + b0; v.y = acc[mi][ni][1] + b1;
                *(float2*)&orow0[col] = v;
            }
            if (orow1) {
                float2 v; v.x = acc[mi][ni][2] + b0; v.y = acc[mi][ni][3] + b1;
                *(float2*)&orow1[col] = v;
            }
        }
    }
}

// ---------------- launch ----------------
extern "C" void kernel_launch(void* const* d_in, const int* in_sizes, int n_in,
                              void* d_out, int out_size) {
    const float* features = (const float*)d_in[0];
    const int*   captions = (const int*)  d_in[1];
    const float* embw     = (const float*)d_in[2];
    const float* Wf       = (const float*)d_in[3];
    const float* bf       = (const float*)d_in[4];
    const float* Wi       = (const float*)d_in[5];
    const float* bi       = (const float*)d_in[6];
    const float* Wc       = (const float*)d_in[7];
    const float* bc       = (const float*)d_in[8];
    const float* Wo       = (const float*)d_in[9];
    const float* bo       = (const float*)d_in[10];
    const float* out_w    = (const float*)d_in[11];
    const float* out_b    = (const float*)d_in[12];
    const float* ihw      = (const float*)d_in[13];
    const float* ihb      = (const float*)d_in[14];
    const float* icw      = (const float*)d_in[15];
    const float* icb      = (const float*)d_in[16];
    float* out = (float*)d_out;

    cudaFuncSetAttribute(logits_hmma_kernel,
                         cudaFuncAttributeMaxDynamicSharedMemorySize, SMEM_DYN);

    init_kernel<<<BATCH, 256>>>(features, ihw, ihb, icw, icb);

    {
        int total = VOCAB * 512;
        convB_kernel<<<(total + 255) / 256, 256>>>(out_w);
    }

    for (int t = 0; t < STEPS; t++) {
        int pr = t & 1;
        int pw = pr ^ 1;
        for (int l = 0; l < NLAYERS; l++) {
            size_t wofs = (size_t)l * HIDDEN * COMBK;
            size_t bofs = (size_t)l * HIDDEN;
            lstm_step_kernel<<<HIDDEN / UPB, 128>>>(
                embw, captions,
                Wf + wofs, Wi + wofs, Wo + wofs, Wc + wofs,
                bf + bofs, bi + bofs, bo + bofs, bc + bofs,
                l, t, pr, pw);
        }
    }

    {
        int total = MROWS * 512;
        convA_kernel<<<(total + 255) / 256, 256>>>();
    }

    dim3 grid(VOCAB / 128, MPAD / 128);   // 250 x 16
    logits_hmma_kernel<<<grid, 256, SMEM_DYN>>>(out_b, out);
}

// round 5
// speedup vs baseline: 1.6827x; 1.2493x over previous
#include <cuda_runtime.h>
#include <cuda_bf16.h>
#include <cuda_fp16.h>
#include <math.h>
#include <stdint.h>

// Problem constants
#define EMBED   512
#define HIDDEN  512
#define VOCAB   32000
#define NLAYERS 2
#define BATCH   32
#define SEQ     64
#define STEPS   (SEQ - 1)          // 63
#define MROWS   (STEPS * BATCH)    // 2016
#define MPAD    2048
#define KP      1536               // split-K: [Ahi|Ahi|Alo] x [Bhi|Blo|Bhi]
#define GUNITS  2048               // 4 gates x 512
#define SCAN_G  256                // scan grid (blocks); all co-resident

// ---------------- scratch (no allocations allowed) ----------------
__device__ __half g_A[(size_t)MPAD * KP];          // 6.3 MB  A-side split
__device__ __half g_B[(size_t)VOCAB * KP];         // 98 MB   out_w split
__device__ __half g_BW[(size_t)NLAYERS * GUNITS * KP]; // 12.6 MB Wx split
__device__ float  g_X[(size_t)MPAD * GUNITS];      // 16.8 MB x-part preacts
__device__ float  g_h0rows[MROWS * HIDDEN];        // 4 MB  h of layer0, rows (t*32+b)
__device__ float  g_h1rows[MROWS * HIDDEN];        // 4 MB  h of layer1
__device__ float  g_hT0[2][HIDDEN * BATCH];        // ping-pong h, transposed [k][b]
__device__ float  g_hT1[2][HIDDEN * BATCH];
__device__ float  g_c0T[HIDDEN * BATCH];
__device__ unsigned g_bar[2];                      // grid-barrier counters (self-resetting)
__device__ unsigned g_fin[2];

__device__ __forceinline__ float sigmoidf_(float x) {
    return 1.0f / (1.0f + expf(-x));
}

// ================= PTX helpers (baseline ISA only) =================
static __device__ __forceinline__ uint32_t smem_u32(const void* p) {
    uint32_t a;
    asm("{ .reg .u64 t; cvta.to.shared.u64 t, %1; cvt.u32.u64 %0, t; }" : "=r"(a) : "l"(p));
    return a;
}
static __device__ __forceinline__ void cp_async16(uint32_t dst, const void* src) {
    asm volatile("cp.async.cg.shared.global [%0], [%1], 16;" :: "r"(dst), "l"(src));
}
#define CP_COMMIT()  asm volatile("cp.async.commit_group;" ::: "memory")
#define CP_WAIT(n)   asm volatile("cp.async.wait_group %0;" :: "n"(n) : "memory")

static __device__ __forceinline__ void ldsm4(uint32_t* r, uint32_t addr) {
    asm volatile("ldmatrix.sync.aligned.m8n8.x4.shared.b16 {%0,%1,%2,%3}, [%4];"
                 : "=r"(r[0]), "=r"(r[1]), "=r"(r[2]), "=r"(r[3]) : "r"(addr));
}
static __device__ __forceinline__ void mma16816(float* c, const uint32_t* a,
                                                uint32_t b0, uint32_t b1) {
    asm volatile("mma.sync.aligned.m16n8k16.row.col.f32.f16.f16.f32 "
                 "{%0,%1,%2,%3}, {%4,%5,%6,%7}, {%8,%9}, {%0,%1,%2,%3};"
                 : "+f"(c[0]), "+f"(c[1]), "+f"(c[2]), "+f"(c[3])
                 : "r"(a[0]), "r"(a[1]), "r"(a[2]), "r"(a[3]), "r"(b0), "r"(b1));
}

// ---------------- init: h0/c0 -> transposed state buffers ----------------
__global__ void init_kernel(const float* __restrict__ features,
                            const float* __restrict__ ihw, const float* __restrict__ ihb,
                            const float* __restrict__ icw, const float* __restrict__ icb) {
    __shared__ float feat[EMBED];
    int b = blockIdx.x;
    for (int i = threadIdx.x; i < EMBED; i += blockDim.x)
        feat[i] = features[b * EMBED + i];
    __syncthreads();

    for (int j = threadIdx.x; j < HIDDEN; j += blockDim.x) {
        float ah = ihb[j];
        float ac = icb[j];
        const float4* wh = (const float4*)(ihw + (size_t)j * EMBED);
        const float4* wc = (const float4*)(icw + (size_t)j * EMBED);
        #pragma unroll 4
        for (int e4 = 0; e4 < EMBED / 4; e4++) {
            float4 h4 = wh[e4];
            float4 c4 = wc[e4];
            const float* f = &feat[e4 * 4];
            ah += f[0]*h4.x + f[1]*h4.y + f[2]*h4.z + f[3]*h4.w;
            ac += f[0]*c4.x + f[1]*c4.y + f[2]*c4.z + f[3]*c4.w;
        }
        g_hT0[0][j * BATCH + b] = ah;
        g_hT1[0][j * BATCH + b] = ah;
        g_c0T[j * BATCH + b]    = ac;
    }
}

// ---------------- conversions ----------------
// out_w -> g_B  (B-style: [hi | lo | hi])
__global__ __launch_bounds__(256)
void convB_kernel(const float* __restrict__ w) {
    size_t idx = (size_t)blockIdx.x * blockDim.x + threadIdx.x;
    if (idx >= (size_t)VOCAB * 512) return;
    int n = (int)(idx >> 9);
    int k = (int)(idx & 511);
    float x = w[idx];
    __half hi = __float2half_rn(x);
    __half lo = __float2half_rn(x - __half2float(hi));
    size_t base = (size_t)n * KP;
    g_B[base + k]        = hi;
    g_B[base + 512 + k]  = lo;
    g_B[base + 1024 + k] = hi;
}

// Wx (x-part of gate weights, both layers) -> g_BW (B-style)
// gate row r = g*512 + j ; source Wg[l][j][0:512]
__global__ __launch_bounds__(256)
void convWx_kernel(const float* __restrict__ Wf, const float* __restrict__ Wi,
                   const float* __restrict__ Wo, const float* __restrict__ Wc) {
    size_t idx = (size_t)blockIdx.x * blockDim.x + threadIdx.x;
    if (idx >= (size_t)NLAYERS * GUNITS * 512) return;
    int k = (int)(idx & 511);
    int r = (int)((idx >> 9) & (GUNITS - 1));
    int l = (int)(idx >> 20);              // 2048*512 = 2^20
    int g = r >> 9;
    int j = r & 511;
    const float* W = (g == 0) ? Wf : (g == 1) ? Wi : (g == 2) ? Wo : Wc;
    float x = W[(size_t)l * HIDDEN * 1024 + (size_t)j * 1024 + k];
    __half hi = __float2half_rn(x);
    __half lo = __float2half_rn(x - __half2float(hi));
    size_t base = ((size_t)l * GUNITS + r) * KP;
    g_BW[base + k]        = hi;
    g_BW[base + 512 + k]  = lo;
    g_BW[base + 1024 + k] = hi;
}

// embeddings gather -> g_A (A-style: [hi | hi | lo]); row m = t*32+b
__global__ __launch_bounds__(256)
void embA_kernel(const int* __restrict__ captions, const float* __restrict__ embw) {
    size_t idx = (size_t)blockIdx.x * blockDim.x + threadIdx.x;
    if (idx >= (size_t)MROWS * 512) return;
    int m = (int)(idx >> 9);
    int k = (int)(idx & 511);
    int t = m >> 5, b = m & 31;
    int tok = captions[b * SEQ + t];
    float x = embw[(size_t)tok * EMBED + k];
    __half hi = __float2half_rn(x);
    __half lo = __float2half_rn(x - __half2float(hi));
    size_t base = (size_t)m * KP;
    g_A[base + k]        = hi;
    g_A[base + 512 + k]  = hi;
    g_A[base + 1024 + k] = lo;
}

// h rows (fp32, MROWS x 512) -> g_A (A-style)
__global__ __launch_bounds__(256)
void convA_kernel(const float* __restrict__ src) {
    size_t idx = (size_t)blockIdx.x * blockDim.x + threadIdx.x;
    if (idx >= (size_t)MROWS * 512) return;
    int m = (int)(idx >> 9);
    int k = (int)(idx & 511);
    float x = src[idx];
    __half hi = __float2half_rn(x);
    __half lo = __float2half_rn(x - __half2float(hi));
    size_t base = (size_t)m * KP;
    g_A[base + k]        = hi;
    g_A[base + 512 + k]  = hi;
    g_A[base + 1024 + k] = lo;
}

// ---------------- generic split HMMA GEMM: C[MPAD x N] = g_A @ Bsrc^T (+bias) ----------------
#define GBK       64
#define GNCH      (KP / GBK)         // 24
#define GTILE_B   16384              // 128 rows * 128 B
#define GBUF_B    (2 * GTILE_B)
#define SMEM_DYN  (2 * GBUF_B + 512)

__global__ __launch_bounds__(256)
void gemm_split_kernel(const __half* __restrict__ Bsrc, const float* __restrict__ bias,
                       float* __restrict__ C, int N, int permute) {
    extern __shared__ __align__(128) char sm[];
    const uint32_t smu = smem_u32(sm);
    float* bias_s = (float*)(sm + 2 * GBUF_B);

    const int tid  = threadIdx.x;
    const int wid  = tid >> 5;
    const int lane = tid & 31;
    const int n0 = blockIdx.x * 128;
    const int m0 = blockIdx.y * 128;

    const int warp_m = (wid >> 1) * 32;
    const int warp_n = (wid & 1) * 64;

    if (tid < 128) bias_s[tid] = bias ? bias[n0 + tid] : 0.0f;

    auto load_chunk = [&](int c) {
        const int buf = c & 1;
        const uint32_t sA = smu + buf * GBUF_B;
        const uint32_t sB = sA + GTILE_B;
        const __half* Ag = g_A + (size_t)m0 * KP + c * GBK;
        const __half* Bg = Bsrc + (size_t)n0 * KP + c * GBK;
        #pragma unroll
        for (int i = 0; i < 4; i++) {
            int idx = i * 256 + tid;
            int r  = idx >> 3;
            int ch = idx & 7;
            uint32_t dst = (uint32_t)(r * 128) + (((uint32_t)(ch ^ (r & 7))) << 4);
            cp_async16(sA + dst, Ag + (size_t)r * KP + ch * 8);
            cp_async16(sB + dst, Bg + (size_t)r * KP + ch * 8);
        }
        CP_COMMIT();
    };

    float acc[2][8][4];
    #pragma unroll
    for (int mi = 0; mi < 2; mi++)
        #pragma unroll
        for (int ni = 0; ni < 8; ni++)
            #pragma unroll
            for (int q = 0; q < 4; q++) acc[mi][ni][q] = 0.f;

    load_chunk(0);
    load_chunk(1);

    for (int c = 0; c < GNCH; c++) {
        if (c + 1 < GNCH) { CP_WAIT(1); } else { CP_WAIT(0); }
        __syncthreads();

        const int buf = c & 1;
        const uint32_t sA = smu + buf * GBUF_B;
        const uint32_t sB = sA + GTILE_B;

        #pragma unroll
        for (int ks = 0; ks < GBK / 16; ks++) {
            uint32_t a[2][4];
            #pragma unroll
            for (int mi = 0; mi < 2; mi++) {
                int row = warp_m + mi * 16 + (lane & 15);
                int kc  = ks * 2 + (lane >> 4);
                uint32_t addr = sA + row * 128 + (((uint32_t)(kc ^ (row & 7))) << 4);
                ldsm4(a[mi], addr);
            }
            uint32_t bfr[4][4];
            #pragma unroll
            for (int nj = 0; nj < 4; nj++) {
                int row = warp_n + nj * 16 + (lane & 7) + ((lane >> 4) << 3);
                int kc  = ks * 2 + ((lane >> 3) & 1);
                uint32_t addr = sB + row * 128 + (((uint32_t)(kc ^ (row & 7))) << 4);
                ldsm4(bfr[nj], addr);
            }
            #pragma unroll
            for (int mi = 0; mi < 2; mi++)
                #pragma unroll
                for (int ni = 0; ni < 8; ni++) {
                    const uint32_t* bp = &bfr[ni >> 1][(ni & 1) * 2];
                    mma16816(acc[mi][ni], a[mi], bp[0], bp[1]);
                }
        }
        __syncthreads();
        if (c + 2 < GNCH) load_chunk(c + 2);
    }

    #pragma unroll
    for (int mi = 0; mi < 2; mi++) {
        int r0 = m0 + warp_m + mi * 16 + (lane >> 2);
        int r1 = r0 + 8;
        float* orow0 = nullptr;
        float* orow1 = nullptr;
        if (permute) {
            if (r0 < MROWS) {
                int bb = r0 & 31, tt = r0 >> 5;
                orow0 = C + (size_t)(bb * STEPS + tt) * N + n0;
            }
            if (r1 < MROWS) {
                int bb = r1 & 31, tt = r1 >> 5;
                orow1 = C + (size_t)(bb * STEPS + tt) * N + n0;
            }
        } else {
            orow0 = C + (size_t)r0 * N + n0;
            orow1 = C + (size_t)r1 * N + n0;
        }
        #pragma unroll
        for (int ni = 0; ni < 8; ni++) {
            int col = warp_n + ni * 8 + (lane & 3) * 2;
            float b0 = bias_s[col];
            float b1 = bias_s[col + 1];
            if (orow0) {
                float2 v; v.x = acc[mi][ni][0] + b0; v.y = acc[mi][ni][1] + b1;
                *(float2*)&orow0[col] = v;
            }
            if (orow1) {
                float2 v; v.x = acc[mi][ni][2] + b0; v.y = acc[mi][ni][3] + b1;
                *(float2*)&orow1[col] = v;
            }
        }
    }
}

// ---------------- persistent scan: 63 steps of one layer ----------------
// Grid = 256 blocks x 128 threads, all co-resident; grid barrier per step.
// Block owns units j in {2*bid, 2*bid+1} for all 4 gates (8 weight rows, smem-resident).
// Thread (b = tid&31, q = tid>>5 = gate) accumulates h-part for both units.
__global__ __launch_bounds__(128, 2)
void scan_kernel(const float* __restrict__ Wf, const float* __restrict__ Wi,
                 const float* __restrict__ Wo, const float* __restrict__ Wc,
                 const float* __restrict__ bfv, const float* __restrict__ biv,
                 const float* __restrict__ bov, const float* __restrict__ bcv,
                 const float* __restrict__ X, float* __restrict__ hT,
                 const float* __restrict__ c0T, float* __restrict__ hrows,
                 int layer) {
    __shared__ float w_s[4][2][HIDDEN];    // 16 KB
    __shared__ float ex_s[4][2][BATCH];    // 1 KB
    __shared__ float bias_s[4][2];

    const int tid = threadIdx.x;
    const int bid = blockIdx.x;
    const int b = tid & 31;
    const int q = tid >> 5;

    // load weight slice (h-part) into smem: rows (g, jj) = W_g[2*bid+jj][512:1024]
    #pragma unroll
    for (int pass = 0; pass < 8; pass++) {
        int g = pass >> 1, jj = pass & 1;
        const float* W = (g == 0) ? Wf : (g == 1) ? Wi : (g == 2) ? Wo : Wc;
        const float* src = W + (size_t)(2 * bid + jj) * 1024 + 512;
        *(float4*)&w_s[g][jj][tid * 4] = *(const float4*)&src[tid * 4];
    }
    if (tid < 8) {
        int g = tid >> 1, jj = tid & 1;
        const float* Bv = (g == 0) ? bfv : (g == 1) ? biv : (g == 2) ? bov : bcv;
        bias_s[g][jj] = Bv[2 * bid + jj];
    }
    float c_reg = 0.f;
    if (q < 2) c_reg = c0T[(2 * bid + q) * BATCH + b];
    __syncthreads();

    const unsigned G = gridDim.x;

    for (int t = 0; t < STEPS; t++) {
        const int p = t & 1;
        const float* hc = hT + p * (HIDDEN * BATCH);
        float* hn = hT + (p ^ 1) * (HIDDEN * BATCH);

        float acc0 = 0.f, acc1 = 0.f;
        #pragma unroll 4
        for (int k = 0; k < HIDDEN; k += 4) {
            float h0v = hc[(k + 0) * BATCH + b];
            float h1v = hc[(k + 1) * BATCH + b];
            float h2v = hc[(k + 2) * BATCH + b];
            float h3v = hc[(k + 3) * BATCH + b];
            float4 wa = *(const float4*)&w_s[q][0][k];
            float4 wb = *(const float4*)&w_s[q][1][k];
            acc0 += h0v * wa.x + h1v * wa.y + h2v * wa.z + h3v * wa.w;
            acc1 += h0v * wb.x + h1v * wb.y + h2v * wb.z + h3v * wb.w;
        }
        const float* xrow = X + (size_t)(t * BATCH + b) * GUNITS + q * 512 + 2 * bid;
        ex_s[q][0][b] = acc0 + bias_s[q][0] + xrow[0];
        ex_s[q][1][b] = acc1 + bias_s[q][1] + xrow[1];
        __syncthreads();

        if (q < 2) {
            float f  = sigmoidf_(ex_s[0][q][b]);
            float i  = sigmoidf_(ex_s[1][q][b]);
            float o  = sigmoidf_(ex_s[2][q][b]);
            float ct = tanhf    (ex_s[3][q][b]);
            c_reg = f * c_reg + i * ct;
            float h = o * tanhf(c_reg);
            hn[(2 * bid + q) * BATCH + b] = h;
            hrows[(size_t)(t * BATCH + b) * HIDDEN + 2 * bid + q] = h;
        }
        __syncthreads();

        // grid barrier
        if (tid == 0) {
            __threadfence();
            atomicAdd(&g_bar[layer], 1u);
            unsigned target = (unsigned)(t + 1) * G;
            volatile unsigned* pb = &g_bar[layer];
            while (*pb < target) { __nanosleep(32); }
            __threadfence();
        }
        __syncthreads();
    }

    // reset counters for next launch/replay (last block to finish does it)
    if (tid == 0) {
        unsigned v = atomicAdd(&g_fin[layer], 1u);
        if (v == G - 1) {
            g_bar[layer] = 0;
            g_fin[layer] = 0;
            __threadfence();
        }
    }
}

// ---------------- launch ----------------
extern "C" void kernel_launch(void* const* d_in, const int* in_sizes, int n_in,
                              void* d_out, int out_size) {
    const float* features = (const float*)d_in[0];
    const int*   captions = (const int*)  d_in[1];
    const float* embw     = (const float*)d_in[2];
    const float* Wf       = (const float*)d_in[3];
    const float* bf       = (const float*)d_in[4];
    const float* Wi       = (const float*)d_in[5];
    const float* bi       = (const float*)d_in[6];
    const float* Wc       = (const float*)d_in[7];
    const float* bc       = (const float*)d_in[8];
    const float* Wo       = (const float*)d_in[9];
    const float* bo       = (const float*)d_in[10];
    const float* out_w    = (const float*)d_in[11];
    const float* out_b    = (const float*)d_in[12];
    const float* ihw      = (const float*)d_in[13];
    const float* ihb      = (const float*)d_in[14];
    const float* icw      = (const float*)d_in[15];
    const float* icb      = (const float*)d_in[16];
    float* out = (float*)d_out;

    cudaFuncSetAttribute(gemm_split_kernel,
                         cudaFuncAttributeMaxDynamicSharedMemorySize, SMEM_DYN);

    __half* g_B_ptr;  cudaGetSymbolAddress((void**)&g_B_ptr,  g_B);
    __half* g_BW_ptr; cudaGetSymbolAddress((void**)&g_BW_ptr, g_BW);
    float*  g_X_ptr;  cudaGetSymbolAddress((void**)&g_X_ptr,  g_X);
    float*  g_h0_ptr; cudaGetSymbolAddress((void**)&g_h0_ptr, g_h0rows);
    float*  g_h1_ptr; cudaGetSymbolAddress((void**)&g_h1_ptr, g_h1rows);
    float*  g_hT0_p;  cudaGetSymbolAddress((void**)&g_hT0_p,  g_hT0);
    float*  g_hT1_p;  cudaGetSymbolAddress((void**)&g_hT1_p,  g_hT1);
    float*  g_c0T_p;  cudaGetSymbolAddress((void**)&g_c0T_p,  g_c0T);

    // 1. init state
    init_kernel<<<BATCH, 256>>>(features, ihw, ihb, icw, icb);

    // 2. conversions (weights; independent of recurrence)
    convB_kernel<<<(VOCAB * 512 + 255) / 256, 256>>>(out_w);
    convWx_kernel<<<(NLAYERS * GUNITS * 512 + 255) / 256, 256>>>(Wf, Wi, Wo, Wc);
    embA_kernel<<<(MROWS * 512 + 255) / 256, 256>>>(captions, embw);

    // 3. X0 = emb @ Wx0^T
    {
        dim3 grid(GUNITS / 128, MPAD / 128);  // 16 x 16
        gemm_split_kernel<<<grid, 256, SMEM_DYN>>>(g_BW_ptr, nullptr, g_X_ptr, GUNITS, 0);
    }

    // 4. layer-0 scan (persistent)
    scan_kernel<<<SCAN_G, 128>>>(Wf, Wi, Wo, Wc, bf, bi, bo, bc,
                                 g_X_ptr, g_hT0_p, g_c0T_p, g_h0_ptr, 0);

    // 5. X1 = h0 @ Wx1^T
    convA_kernel<<<(MROWS * 512 + 255) / 256, 256>>>(g_h0_ptr);
    {
        dim3 grid(GUNITS / 128, MPAD / 128);
        gemm_split_kernel<<<grid, 256, SMEM_DYN>>>(g_BW_ptr + (size_t)GUNITS * KP,
                                                   nullptr, g_X_ptr, GUNITS, 0);
    }

    // 6. layer-1 scan
    scan_kernel<<<SCAN_G, 128>>>(Wf + 512 * 1024, Wi + 512 * 1024,
                                 Wo + 512 * 1024, Wc + 512 * 1024,
                                 bf + 512, bi + 512, bo + 512, bc + 512,
                                 g_X_ptr, g_hT1_p, g_c0T_p, g_h1_ptr, 1);

    // 7. logits = h1 @ out_w^T + out_b  (permuted store)
    convA_kernel<<<(MROWS * 512 + 255) / 256, 256>>>(g_h1_ptr);
    {
        dim3 grid(VOCAB / 128, MPAD / 128);   // 250 x 16
        gemm_split_kernel<<<grid, 256, SMEM_DYN>>>(g_B_ptr, out_b, out, VOCAB, 1);
    }
}

// round 6
// speedup vs baseline: 2.1713x; 1.2904x over previous
#include <cuda_runtime.h>
#include <cuda_bf16.h>
#include <cuda_fp16.h>
#include <math.h>
#include <stdint.h>

// Problem constants
#define EMBED   512
#define HIDDEN  512
#define VOCAB   32000
#define NLAYERS 2
#define BATCH   32
#define SEQ     64
#define STEPS   (SEQ - 1)          // 63
#define MROWS   (STEPS * BATCH)    // 2016
#define MPAD    2048
#define KP      1024               // 2-term split: [Ahi|Alo] x [Bhi|Bhi]
#define GUNITS  2048               // 4 gates x 512
#define SCAN_G  256                // scan grid (blocks); all co-resident

// ---------------- scratch (no allocations allowed) ----------------
__device__ __half g_A[(size_t)MPAD * KP];              // 4.2 MB  A-side split
__device__ __half g_B[(size_t)VOCAB * KP];             // 65 MB   out_w split
__device__ __half g_BW[(size_t)NLAYERS * GUNITS * KP]; // 8.4 MB  Wx split
__device__ float  g_X[(size_t)MPAD * GUNITS];          // 16.8 MB x-part preacts
__device__ float  g_hT0[2][HIDDEN * BATCH];            // ping-pong h, transposed [k][b]
__device__ float  g_hT1[2][HIDDEN * BATCH];
__device__ float  g_c0T[HIDDEN * BATCH];
__device__ unsigned g_bar[2];                          // grid-barrier counters (self-resetting)
__device__ unsigned g_fin[2];

__device__ __forceinline__ float sigmoidf_(float x) {
    return 1.0f / (1.0f + expf(-x));
}

// ================= PTX helpers (baseline ISA only) =================
static __device__ __forceinline__ uint32_t smem_u32(const void* p) {
    uint32_t a;
    asm("{ .reg .u64 t; cvta.to.shared.u64 t, %1; cvt.u32.u64 %0, t; }" : "=r"(a) : "l"(p));
    return a;
}
static __device__ __forceinline__ void cp_async16(uint32_t dst, const void* src) {
    asm volatile("cp.async.cg.shared.global [%0], [%1], 16;" :: "r"(dst), "l"(src));
}
#define CP_COMMIT()  asm volatile("cp.async.commit_group;" ::: "memory")
#define CP_WAIT(n)   asm volatile("cp.async.wait_group %0;" :: "n"(n) : "memory")

static __device__ __forceinline__ void ldsm4(uint32_t* r, uint32_t addr) {
    asm volatile("ldmatrix.sync.aligned.m8n8.x4.shared.b16 {%0,%1,%2,%3}, [%4];"
                 : "=r"(r[0]), "=r"(r[1]), "=r"(r[2]), "=r"(r[3]) : "r"(addr));
}
static __device__ __forceinline__ void mma16816(float* c, const uint32_t* a,
                                                uint32_t b0, uint32_t b1) {
    asm volatile("mma.sync.aligned.m16n8k16.row.col.f32.f16.f16.f32 "
                 "{%0,%1,%2,%3}, {%4,%5,%6,%7}, {%8,%9}, {%0,%1,%2,%3};"
                 : "+f"(c[0]), "+f"(c[1]), "+f"(c[2]), "+f"(c[3])
                 : "r"(a[0]), "r"(a[1]), "r"(a[2]), "r"(a[3]), "r"(b0), "r"(b1));
}

// ---------------- init: h0/c0 -> transposed state buffers ----------------
__global__ void init_kernel(const float* __restrict__ features,
                            const float* __restrict__ ihw, const float* __restrict__ ihb,
                            const float* __restrict__ icw, const float* __restrict__ icb) {
    __shared__ float feat[EMBED];
    int b = blockIdx.x;
    for (int i = threadIdx.x; i < EMBED; i += blockDim.x)
        feat[i] = features[b * EMBED + i];
    __syncthreads();

    for (int j = threadIdx.x; j < HIDDEN; j += blockDim.x) {
        float ah = ihb[j];
        float ac = icb[j];
        const float4* wh = (const float4*)(ihw + (size_t)j * EMBED);
        const float4* wc = (const float4*)(icw + (size_t)j * EMBED);
        #pragma unroll 4
        for (int e4 = 0; e4 < EMBED / 4; e4++) {
            float4 h4 = wh[e4];
            float4 c4 = wc[e4];
            const float* f = &feat[e4 * 4];
            ah += f[0]*h4.x + f[1]*h4.y + f[2]*h4.z + f[3]*h4.w;
            ac += f[0]*c4.x + f[1]*c4.y + f[2]*c4.z + f[3]*c4.w;
        }
        g_hT0[0][j * BATCH + b] = ah;
        g_hT1[0][j * BATCH + b] = ah;
        g_c0T[j * BATCH + b]    = ac;
    }
}

// ---------------- conversions ----------------
// out_w -> g_B  (B-style: [hi | hi])
__global__ __launch_bounds__(256)
void convB_kernel(const float* __restrict__ w) {
    size_t idx = (size_t)blockIdx.x * blockDim.x + threadIdx.x;
    if (idx >= (size_t)VOCAB * 512) return;
    int n = (int)(idx >> 9);
    int k = (int)(idx & 511);
    __half hi = __float2half_rn(w[idx]);
    size_t base = (size_t)n * KP;
    g_B[base + k]       = hi;
    g_B[base + 512 + k] = hi;
}

// Wx (x-part of gate weights, both layers) -> g_BW (B-style [hi|hi])
// gate row r = g*512 + j ; source Wg[l][j][0:512]
__global__ __launch_bounds__(256)
void convWx_kernel(const float* __restrict__ Wf, const float* __restrict__ Wi,
                   const float* __restrict__ Wo, const float* __restrict__ Wc) {
    size_t idx = (size_t)blockIdx.x * blockDim.x + threadIdx.x;
    if (idx >= (size_t)NLAYERS * GUNITS * 512) return;
    int k = (int)(idx & 511);
    int r = (int)((idx >> 9) & (GUNITS - 1));
    int l = (int)(idx >> 20);              // 2048*512 = 2^20
    int g = r >> 9;
    int j = r & 511;
    const float* W = (g == 0) ? Wf : (g == 1) ? Wi : (g == 2) ? Wo : Wc;
    __half hi = __float2half_rn(W[(size_t)l * HIDDEN * 1024 + (size_t)j * 1024 + k]);
    size_t base = ((size_t)l * GUNITS + r) * KP;
    g_BW[base + k]       = hi;
    g_BW[base + 512 + k] = hi;
}

// embeddings gather -> g_A (A-style: [hi | lo]); row m = t*32+b
__global__ __launch_bounds__(256)
void embA_kernel(const int* __restrict__ captions, const float* __restrict__ embw) {
    size_t idx = (size_t)blockIdx.x * blockDim.x + threadIdx.x;
    if (idx >= (size_t)MROWS * 512) return;
    int m = (int)(idx >> 9);
    int k = (int)(idx & 511);
    int t = m >> 5, b = m & 31;
    int tok = captions[b * SEQ + t];
    float x = embw[(size_t)tok * EMBED + k];
    __half hi = __float2half_rn(x);
    __half lo = __float2half_rn(x - __half2float(hi));
    size_t base = (size_t)m * KP;
    g_A[base + k]       = hi;
    g_A[base + 512 + k] = lo;
}

// ---------------- generic split HMMA GEMM: C[MPAD x N] = g_A @ Bsrc^T (+bias) ----------------
#define GBK       64
#define GNCH      (KP / GBK)         // 16
#define GTILE_B   16384              // 128 rows * 128 B
#define GBUF_B    (2 * GTILE_B)
#define SMEM_DYN  (2 * GBUF_B + 512)

__global__ __launch_bounds__(256)
void gemm_split_kernel(const __half* __restrict__ Bsrc, const float* __restrict__ bias,
                       float* __restrict__ C, int N, int permute) {
    extern __shared__ __align__(128) char sm[];
    const uint32_t smu = smem_u32(sm);
    float* bias_s = (float*)(sm + 2 * GBUF_B);

    const int tid  = threadIdx.x;
    const int wid  = tid >> 5;
    const int lane = tid & 31;
    const int n0 = blockIdx.x * 128;
    const int m0 = blockIdx.y * 128;

    const int warp_m = (wid >> 1) * 32;
    const int warp_n = (wid & 1) * 64;

    if (tid < 128) bias_s[tid] = bias ? bias[n0 + tid] : 0.0f;

    auto load_chunk = [&](int c) {
        const int buf = c & 1;
        const uint32_t sA = smu + buf * GBUF_B;
        const uint32_t sB = sA + GTILE_B;
        const __half* Ag = g_A + (size_t)m0 * KP + c * GBK;
        const __half* Bg = Bsrc + (size_t)n0 * KP + c * GBK;
        #pragma unroll
        for (int i = 0; i < 4; i++) {
            int idx = i * 256 + tid;
            int r  = idx >> 3;
            int ch = idx & 7;
            uint32_t dst = (uint32_t)(r * 128) + (((uint32_t)(ch ^ (r & 7))) << 4);
            cp_async16(sA + dst, Ag + (size_t)r * KP + ch * 8);
            cp_async16(sB + dst, Bg + (size_t)r * KP + ch * 8);
        }
        CP_COMMIT();
    };

    float acc[2][8][4];
    #pragma unroll
    for (int mi = 0; mi < 2; mi++)
        #pragma unroll
        for (int ni = 0; ni < 8; ni++)
            #pragma unroll
            for (int q = 0; q < 4; q++) acc[mi][ni][q] = 0.f;

    load_chunk(0);
    load_chunk(1);

    for (int c = 0; c < GNCH; c++) {
        if (c + 1 < GNCH) { CP_WAIT(1); } else { CP_WAIT(0); }
        __syncthreads();

        const int buf = c & 1;
        const uint32_t sA = smu + buf * GBUF_B;
        const uint32_t sB = sA + GTILE_B;

        #pragma unroll
        for (int ks = 0; ks < GBK / 16; ks++) {
            uint32_t a[2][4];
            #pragma unroll
            for (int mi = 0; mi < 2; mi++) {
                int row = warp_m + mi * 16 + (lane & 15);
                int kc  = ks * 2 + (lane >> 4);
                uint32_t addr = sA + row * 128 + (((uint32_t)(kc ^ (row & 7))) << 4);
                ldsm4(a[mi], addr);
            }
            uint32_t bfr[4][4];
            #pragma unroll
            for (int nj = 0; nj < 4; nj++) {
                int row = warp_n + nj * 16 + (lane & 7) + ((lane >> 4) << 3);
                int kc  = ks * 2 + ((lane >> 3) & 1);
                uint32_t addr = sB + row * 128 + (((uint32_t)(kc ^ (row & 7))) << 4);
                ldsm4(bfr[nj], addr);
            }
            #pragma unroll
            for (int mi = 0; mi < 2; mi++)
                #pragma unroll
                for (int ni = 0; ni < 8; ni++) {
                    const uint32_t* bp = &bfr[ni >> 1][(ni & 1) * 2];
                    mma16816(acc[mi][ni], a[mi], bp[0], bp[1]);
                }
        }
        __syncthreads();
        if (c + 2 < GNCH) load_chunk(c + 2);
    }

    #pragma unroll
    for (int mi = 0; mi < 2; mi++) {
        int r0 = m0 + warp_m + mi * 16 + (lane >> 2);
        int r1 = r0 + 8;
        float* orow0 = nullptr;
        float* orow1 = nullptr;
        if (permute) {
            if (r0 < MROWS) {
                int bb = r0 & 31, tt = r0 >> 5;
                orow0 = C + (size_t)(bb * STEPS + tt) * N + n0;
            }
            if (r1 < MROWS) {
                int bb = r1 & 31, tt = r1 >> 5;
                orow1 = C + (size_t)(bb * STEPS + tt) * N + n0;
            }
        } else {
            orow0 = C + (size_t)r0 * N + n0;
            orow1 = C + (size_t)r1 * N + n0;
        }
        #pragma unroll
        for (int ni = 0; ni < 8; ni++) {
            int col = warp_n + ni * 8 + (lane & 3) * 2;
            float b0 = bias_s[col];
            float b1 = bias_s[col + 1];
            if (orow0) {
                float2 v; v.x = acc[mi][ni][0] + b0; v.y = acc[mi][ni][1] + b1;
                *(float2*)&orow0[col] = v;
            }
            if (orow1) {
                float2 v; v.x = acc[mi][ni][2] + b0; v.y = acc[mi][ni][3] + b1;
                *(float2*)&orow1[col] = v;
            }
        }
    }
}

// ---------------- persistent scan: 63 steps of one layer ----------------
// Grid = 256 blocks x 128 threads, all co-resident; grid barrier per step.
// Block owns units j in {2*bid, 2*bid+1} for all 4 gates (8 weight rows, smem-resident).
// h state staged through smem in 64-k chunks (cuts LDG issue 16x vs per-warp loads).
// Epilogue writes fp16 hi/lo split rows straight into g_A (feeds next GEMM).
__global__ __launch_bounds__(128, 2)
void scan_kernel(const float* __restrict__ Wf, const float* __restrict__ Wi,
                 const float* __restrict__ Wo, const float* __restrict__ Wc,
                 const float* __restrict__ bfv, const float* __restrict__ biv,
                 const float* __restrict__ bov, const float* __restrict__ bcv,
                 const float* __restrict__ X, float* __restrict__ hT,
                 const float* __restrict__ c0T, int layer) {
    __shared__ float w_s[4][2][HIDDEN];              // 16 KB
    __shared__ __align__(16) float h_s[64][BATCH];   // 8 KB staging
    __shared__ float ex_s[4][2][BATCH];              // 1 KB
    __shared__ float bias_s[4][2];

    const int tid = threadIdx.x;
    const int bid = blockIdx.x;
    const int b = tid & 31;
    const int q = tid >> 5;

    // load weight slice (h-part) into smem: rows (g, jj) = W_g[2*bid+jj][512:1024]
    #pragma unroll
    for (int pass = 0; pass < 8; pass++) {
        int g = pass >> 1, jj = pass & 1;
        const float* W = (g == 0) ? Wf : (g == 1) ? Wi : (g == 2) ? Wo : Wc;
        const float* src = W + (size_t)(2 * bid + jj) * 1024 + 512;
        *(float4*)&w_s[g][jj][tid * 4] = *(const float4*)&src[tid * 4];
    }
    if (tid < 8) {
        int g = tid >> 1, jj = tid & 1;
        const float* Bv = (g == 0) ? bfv : (g == 1) ? biv : (g == 2) ? bov : bcv;
        bias_s[g][jj] = Bv[2 * bid + jj];
    }
    float c_reg = 0.f;
    if (q < 2) c_reg = c0T[(2 * bid + q) * BATCH + b];
    __syncthreads();

    const unsigned G = gridDim.x;

    for (int t = 0; t < STEPS; t++) {
        const int p = t & 1;
        const float* hc = hT + p * (HIDDEN * BATCH);
        float* hn = hT + (p ^ 1) * (HIDDEN * BATCH);

        float acc0 = 0.f, acc1 = 0.f;
        for (int cch = 0; cch < 8; cch++) {
            __syncthreads();
            // cooperative stage: 64 k's x 32 b = 2048 floats = 512 float4
            const float4* src = (const float4*)hc + cch * 512;
            float4* dst = (float4*)&h_s[0][0];
            #pragma unroll
            for (int i = 0; i < 4; i++)
                dst[i * 128 + tid] = src[i * 128 + tid];
            __syncthreads();

            const float* wa_base = &w_s[q][0][cch * 64];
            const float* wb_base = &w_s[q][1][cch * 64];
            #pragma unroll
            for (int k = 0; k < 64; k += 4) {
                float h0v = h_s[k + 0][b];
                float h1v = h_s[k + 1][b];
                float h2v = h_s[k + 2][b];
                float h3v = h_s[k + 3][b];
                float4 wa = *(const float4*)&wa_base[k];
                float4 wb = *(const float4*)&wb_base[k];
                acc0 += h0v * wa.x + h1v * wa.y + h2v * wa.z + h3v * wa.w;
                acc1 += h0v * wb.x + h1v * wb.y + h2v * wb.z + h3v * wb.w;
            }
        }
        float2 xr = *(const float2*)&X[(size_t)(t * BATCH + b) * GUNITS + q * 512 + 2 * bid];
        ex_s[q][0][b] = acc0 + bias_s[q][0] + xr.x;
        ex_s[q][1][b] = acc1 + bias_s[q][1] + xr.y;
        __syncthreads();

        if (q < 2) {
            float f  = sigmoidf_(ex_s[0][q][b]);
            float i  = sigmoidf_(ex_s[1][q][b]);
            float o  = sigmoidf_(ex_s[2][q][b]);
            float ct = tanhf    (ex_s[3][q][b]);
            c_reg = f * c_reg + i * ct;
            float h = o * tanhf(c_reg);
            int j = 2 * bid + q;
            hn[j * BATCH + b] = h;
            // fused convA: fp16 hi/lo split row for the downstream GEMM
            __half hhi = __float2half_rn(h);
            __half hlo = __float2half_rn(h - __half2float(hhi));
            size_t ab = (size_t)(t * BATCH + b) * KP + j;
            g_A[ab]       = hhi;
            g_A[ab + 512] = hlo;
        }
        __syncthreads();

        // grid barrier
        if (tid == 0) {
            __threadfence();
            atomicAdd(&g_bar[layer], 1u);
            unsigned target = (unsigned)(t + 1) * G;
            volatile unsigned* pb = &g_bar[layer];
            while (*pb < target) { __nanosleep(32); }
            __threadfence();
        }
        __syncthreads();
    }

    // reset counters for next launch/replay (last block to finish does it)
    if (tid == 0) {
        unsigned v = atomicAdd(&g_fin[layer], 1u);
        if (v == G - 1) {
            g_bar[layer] = 0;
            g_fin[layer] = 0;
            __threadfence();
        }
    }
}

// ---------------- launch ----------------
extern "C" void kernel_launch(void* const* d_in, const int* in_sizes, int n_in,
                              void* d_out, int out_size) {
    const float* features = (const float*)d_in[0];
    const int*   captions = (const int*)  d_in[1];
    const float* embw     = (const float*)d_in[2];
    const float* Wf       = (const float*)d_in[3];
    const float* bf       = (const float*)d_in[4];
    const float* Wi       = (const float*)d_in[5];
    const float* bi       = (const float*)d_in[6];
    const float* Wc       = (const float*)d_in[7];
    const float* bc       = (const float*)d_in[8];
    const float* Wo       = (const float*)d_in[9];
    const float* bo       = (const float*)d_in[10];
    const float* out_w    = (const float*)d_in[11];
    const float* out_b    = (const float*)d_in[12];
    const float* ihw      = (const float*)d_in[13];
    const float* ihb      = (const float*)d_in[14];
    const float* icw      = (const float*)d_in[15];
    const float* icb      = (const float*)d_in[16];
    float* out = (float*)d_out;

    cudaFuncSetAttribute(gemm_split_kernel,
                         cudaFuncAttributeMaxDynamicSharedMemorySize, SMEM_DYN);

    __half* g_B_ptr;  cudaGetSymbolAddress((void**)&g_B_ptr,  g_B);
    __half* g_BW_ptr; cudaGetSymbolAddress((void**)&g_BW_ptr, g_BW);
    float*  g_X_ptr;  cudaGetSymbolAddress((void**)&g_X_ptr,  g_X);
    float*  g_hT0_p;  cudaGetSymbolAddress((void**)&g_hT0_p,  g_hT0);
    float*  g_hT1_p;  cudaGetSymbolAddress((void**)&g_hT1_p,  g_hT1);
    float*  g_c0T_p;  cudaGetSymbolAddress((void**)&g_c0T_p,  g_c0T);

    // 1. init state
    init_kernel<<<BATCH, 256>>>(features, ihw, ihb, icw, icb);

    // 2. conversions (weights; independent of recurrence)
    convB_kernel<<<(VOCAB * 512 + 255) / 256, 256>>>(out_w);
    convWx_kernel<<<(NLAYERS * GUNITS * 512 + 255) / 256, 256>>>(Wf, Wi, Wo, Wc);
    embA_kernel<<<(MROWS * 512 + 255) / 256, 256>>>(captions, embw);

    // 3. X0 = emb @ Wx0^T
    {
        dim3 grid(GUNITS / 128, MPAD / 128);  // 16 x 16
        gemm_split_kernel<<<grid, 256, SMEM_DYN>>>(g_BW_ptr, nullptr, g_X_ptr, GUNITS, 0);
    }

    // 4. layer-0 scan (persistent; writes g_A hi/lo rows for X1)
    scan_kernel<<<SCAN_G, 128>>>(Wf, Wi, Wo, Wc, bf, bi, bo, bc,
                                 g_X_ptr, g_hT0_p, g_c0T_p, 0);

    // 5. X1 = h0 @ Wx1^T
    {
        dim3 grid(GUNITS / 128, MPAD / 128);
        gemm_split_kernel<<<grid, 256, SMEM_DYN>>>(g_BW_ptr + (size_t)GUNITS * KP,
                                                   nullptr, g_X_ptr, GUNITS, 0);
    }

    // 6. layer-1 scan (writes g_A hi/lo rows for logits)
    scan_kernel<<<SCAN_G, 128>>>(Wf + 512 * 1024, Wi + 512 * 1024,
                                 Wo + 512 * 1024, Wc + 512 * 1024,
                                 bf + 512, bi + 512, bo + 512, bc + 512,
                                 g_X_ptr, g_hT1_p, g_c0T_p, 1);

    // 7. logits = h1 @ out_w^T + out_b  (permuted store)
    {
        dim3 grid(VOCAB / 128, MPAD / 128);   // 250 x 16
        gemm_split_kernel<<<grid, 256, SMEM_DYN>>>(g_B_ptr, out_b, out, VOCAB, 1);
    }
}